// round 2
// baseline (speedup 1.0000x reference)
#include <cuda_runtime.h>
#include <stdint.h>

// Voxel hash table, 2-level trilinear interpolation.
// One warp per query; lane = feature dimension (FDIM = 32).
// Output: (M, 64) float32 — level0 feats in cols [0,32), level1 in [32,64).

#define TSIZE_MASK 0xFFFFFu        // TSIZE = 2^20
#define FDIM 32

// PRIMES % TSIZE (exact int32 math, matches reference PM)
#define PM0 (73856093u % 1048576u)
#define PM1 (19349669u % 1048576u)
#define PM2 (83492791u % 1048576u)

__device__ __forceinline__ void level_query(
    float qx, float qy, float qz, float res,
    const int* __restrict__ h2v,
    const float* __restrict__ feats,
    int lane,
    float& acc)
{
    // IEEE division to bit-match XLA regardless of compiler fast-math flags
    float sx = __fdiv_rn(qx, res);
    float sy = __fdiv_rn(qy, res);
    float sz = __fdiv_rn(qz, res);
    float bfx = floorf(sx), bfy = floorf(sy), bfz = floorf(sz);
    float fx = sx - bfx, fy = sy - bfy, fz = sz - bfz;
    int bx = (int)bfx, by = (int)bfy, bz = (int)bfz;

    // Precompute per-axis hash contributions for offsets {0,1}
    unsigned hx0 = (unsigned)bx * PM0, hx1 = hx0 + PM0;
    unsigned hy0 = (unsigned)by * PM1, hy1 = hy0 + PM1;
    unsigned hz0 = (unsigned)bz * PM2, hz1 = hz0 + PM2;

    // Phase 1: issue all 8 hash-table probes (independent -> MLP=8).
    int v[8];
    {
        unsigned hv;
        hv = (hx0 + hy0 + hz0) & TSIZE_MASK; v[0] = __ldg(h2v + hv);
        hv = (hx0 + hy0 + hz1) & TSIZE_MASK; v[1] = __ldg(h2v + hv);
        hv = (hx0 + hy1 + hz0) & TSIZE_MASK; v[2] = __ldg(h2v + hv);
        hv = (hx0 + hy1 + hz1) & TSIZE_MASK; v[3] = __ldg(h2v + hv);
        hv = (hx1 + hy0 + hz0) & TSIZE_MASK; v[4] = __ldg(h2v + hv);
        hv = (hx1 + hy0 + hz1) & TSIZE_MASK; v[5] = __ldg(h2v + hv);
        hv = (hx1 + hy1 + hz0) & TSIZE_MASK; v[6] = __ldg(h2v + hv);
        hv = (hx1 + hy1 + hz1) & TSIZE_MASK; v[7] = __ldg(h2v + hv);
    }

    // Per-corner trilinear weights
    float wx0 = 1.0f - fx, wx1 = fx;
    float wy0 = 1.0f - fy, wy1 = fy;
    float wz0 = 1.0f - fz, wz1 = fz;
    float w[8];
    w[0] = wx0 * wy0 * wz0;
    w[1] = wx0 * wy0 * wz1;
    w[2] = wx0 * wy1 * wz0;
    w[3] = wx0 * wy1 * wz1;
    w[4] = wx1 * wy0 * wz0;
    w[5] = wx1 * wy0 * wz1;
    w[6] = wx1 * wy1 * wz0;
    w[7] = wx1 * wy1 * wz1;

    // Phase 2: coalesced 128B feature gathers (v is warp-uniform -> no divergence)
    #pragma unroll
    for (int c = 0; c < 8; c++) {
        if (v[c] >= 0) {
            acc = fmaf(w[c], __ldg(feats + (size_t)v[c] * FDIM + lane), acc);
        }
    }
}

__global__ void __launch_bounds__(256)
voxel_hash_kernel(const float* __restrict__ q,
                  const float* __restrict__ feats0,
                  const float* __restrict__ feats1,
                  const int*   __restrict__ h2v0,
                  const int*   __restrict__ h2v1,
                  float* __restrict__ out,
                  int M)
{
    int gtid = blockIdx.x * blockDim.x + threadIdx.x;
    int warp = gtid >> 5;
    int lane = gtid & 31;
    if (warp >= M) return;

    // Broadcast load of the query point (same addr across warp -> 1 request each)
    float qx = __ldg(q + (size_t)warp * 3 + 0);
    float qy = __ldg(q + (size_t)warp * 3 + 1);
    float qz = __ldg(q + (size_t)warp * 3 + 2);

    float acc0 = 0.0f, acc1 = 0.0f;
    level_query(qx, qy, qz, 0.12f, h2v0, feats0, lane, acc0);
    level_query(qx, qy, qz, 0.24f, h2v1, feats1, lane, acc1);

    float* o = out + (size_t)warp * 64;
    o[lane]      = acc0;
    o[lane + 32] = acc1;
}

extern "C" void kernel_launch(void* const* d_in, const int* in_sizes, int n_in,
                              void* d_out, int out_size)
{
    const float* q      = (const float*)d_in[0];
    const float* feats0 = (const float*)d_in[1];
    const float* feats1 = (const float*)d_in[2];
    const int*   h2v0   = (const int*)d_in[3];
    const int*   h2v1   = (const int*)d_in[4];
    float* out = (float*)d_out;

    int M = in_sizes[0] / 3;
    int threads = 256;
    long long total = (long long)M * 32;
    int blocks = (int)((total + threads - 1) / threads);
    voxel_hash_kernel<<<blocks, threads>>>(q, feats0, feats1, h2v0, h2v1, out, M);
}

// round 4
// speedup vs baseline: 1.7343x; 1.7343x over previous
#include <cuda_runtime.h>
#include <stdint.h>

// Voxel hash table, 2-level trilinear interpolation.
// 4 queries per warp; 8 lanes per query; each lane handles a float4 of features.
// Output: (M, 64) float32 — level0 feats in cols [0,32), level1 in [32,64).

#define TSIZE_MASK 0xFFFFFu        // TSIZE = 2^20
#define FDIM 32
#define QPW 4                      // queries per warp
#define LPQ 8                      // lanes per query (8 * float4 = 32 feats)

// PRIMES % TSIZE (exact int32 wraparound math, matches reference PM)
#define PM0 (73856093u % 1048576u)
#define PM1 (19349669u % 1048576u)
#define PM2 (83492791u % 1048576u)

struct LevelScalars {
    unsigned hx0, hx1, hy0, hy1, hz0, hz1;
    float fx, fy, fz;
};

__device__ __forceinline__ void level_prologue(float sx, float sy, float sz, LevelScalars& L)
{
    float bfx = floorf(sx), bfy = floorf(sy), bfz = floorf(sz);
    L.fx = sx - bfx; L.fy = sy - bfy; L.fz = sz - bfz;
    int bx = (int)bfx, by = (int)bfy, bz = (int)bfz;
    L.hx0 = (unsigned)bx * PM0; L.hx1 = L.hx0 + PM0;
    L.hy0 = (unsigned)by * PM1; L.hy1 = L.hy0 + PM1;
    L.hz0 = (unsigned)bz * PM2; L.hz1 = L.hz0 + PM2;
}

__device__ __forceinline__ void level_probe(const LevelScalars& L,
                                            const int* __restrict__ h2v, int v[8])
{
    unsigned xy00 = L.hx0 + L.hy0, xy01 = L.hx0 + L.hy1;
    unsigned xy10 = L.hx1 + L.hy0, xy11 = L.hx1 + L.hy1;
    v[0] = __ldg(h2v + ((xy00 + L.hz0) & TSIZE_MASK));
    v[1] = __ldg(h2v + ((xy00 + L.hz1) & TSIZE_MASK));
    v[2] = __ldg(h2v + ((xy01 + L.hz0) & TSIZE_MASK));
    v[3] = __ldg(h2v + ((xy01 + L.hz1) & TSIZE_MASK));
    v[4] = __ldg(h2v + ((xy10 + L.hz0) & TSIZE_MASK));
    v[5] = __ldg(h2v + ((xy10 + L.hz1) & TSIZE_MASK));
    v[6] = __ldg(h2v + ((xy11 + L.hz0) & TSIZE_MASK));
    v[7] = __ldg(h2v + ((xy11 + L.hz1) & TSIZE_MASK));
}

__device__ __forceinline__ void level_weights(const LevelScalars& L, float w[8])
{
    float wx0 = 1.0f - L.fx, wx1 = L.fx;
    float wy0 = 1.0f - L.fy, wy1 = L.fy;
    float wz0 = 1.0f - L.fz, wz1 = L.fz;
    float a00 = wx0 * wy0, a01 = wx0 * wy1, a10 = wx1 * wy0, a11 = wx1 * wy1;
    w[0] = a00 * wz0; w[1] = a00 * wz1;
    w[2] = a01 * wz0; w[3] = a01 * wz1;
    w[4] = a10 * wz0; w[5] = a10 * wz1;
    w[6] = a11 * wz0; w[7] = a11 * wz1;
}

__device__ __forceinline__ void level_gather(const int v[8], const float w[8],
                                             const float* __restrict__ feats,
                                             int fcol, float4& acc)
{
    #pragma unroll
    for (int c = 0; c < 8; c++) {
        if (v[c] >= 0) {
            float4 f = __ldg((const float4*)(feats + (size_t)v[c] * FDIM + fcol));
            acc.x = fmaf(w[c], f.x, acc.x);
            acc.y = fmaf(w[c], f.y, acc.y);
            acc.z = fmaf(w[c], f.z, acc.z);
            acc.w = fmaf(w[c], f.w, acc.w);
        }
    }
}

__global__ void __launch_bounds__(256)
voxel_hash_kernel(const float* __restrict__ q,
                  const float* __restrict__ feats0,
                  const float* __restrict__ feats1,
                  const int*   __restrict__ h2v0,
                  const int*   __restrict__ h2v1,
                  float4* __restrict__ out4,
                  int M)
{
    int gtid  = blockIdx.x * blockDim.x + threadIdx.x;
    int lane  = gtid & 31;
    int warp  = gtid >> 5;
    int qsub  = lane >> 3;            // which of the 4 queries in this warp
    int flane = lane & 7;             // feature-quad index within the query
    int qidx  = warp * QPW + qsub;
    if (qidx >= M) return;

    float qx = __ldg(q + (size_t)qidx * 3 + 0);
    float qy = __ldg(q + (size_t)qidx * 3 + 1);
    float qz = __ldg(q + (size_t)qidx * 3 + 2);

    // Level 0: IEEE division (bit-match). Level 1: q/0.24 == (q/0.12)*0.5 exactly.
    float sx0 = __fdiv_rn(qx, 0.12f);
    float sy0 = __fdiv_rn(qy, 0.12f);
    float sz0 = __fdiv_rn(qz, 0.12f);
    float sx1 = sx0 * 0.5f, sy1 = sy0 * 0.5f, sz1 = sz0 * 0.5f;

    LevelScalars L0, L1;
    level_prologue(sx0, sy0, sz0, L0);
    level_prologue(sx1, sy1, sz1, L1);

    // Issue all 16 hash-table probes up front (MLP=16).
    int v0[8], v1[8];
    level_probe(L0, h2v0, v0);
    level_probe(L1, h2v1, v1);

    float w0[8], w1[8];
    level_weights(L0, w0);
    level_weights(L1, w1);

    int fcol = flane * 4;
    float4 acc0 = make_float4(0.f, 0.f, 0.f, 0.f);
    float4 acc1 = make_float4(0.f, 0.f, 0.f, 0.f);
    level_gather(v0, w0, feats0, fcol, acc0);
    level_gather(v1, w1, feats1, fcol, acc1);

    // out row = 64 floats = 16 float4; level0 at [0,8), level1 at [8,16).
    size_t obase = (size_t)qidx * 16 + flane;
    out4[obase]     = acc0;
    out4[obase + 8] = acc1;
}

extern "C" void kernel_launch(void* const* d_in, const int* in_sizes, int n_in,
                              void* d_out, int out_size)
{
    const float* q      = (const float*)d_in[0];
    const float* feats0 = (const float*)d_in[1];
    const float* feats1 = (const float*)d_in[2];
    const int*   h2v0   = (const int*)d_in[3];
    const int*   h2v1   = (const int*)d_in[4];
    float4* out = (float4*)d_out;

    int M = in_sizes[0] / 3;
    int threads = 256;
    long long total = (long long)M * LPQ;     // 8 lanes per query
    int blocks = (int)((total + threads - 1) / threads);
    voxel_hash_kernel<<<blocks, threads>>>(q, feats0, feats1, h2v0, h2v1, out, M);
}

// round 5
// speedup vs baseline: 1.8591x; 1.0720x over previous
#include <cuda_runtime.h>
#include <stdint.h>

// Voxel hash table, 2-level trilinear interpolation.
// 4 queries per warp; 8 lanes per query; each lane handles a float4 of features.
// Streaming (evict-first) stores/loads for the 128MB output + query stream so
// the hash tables (~8MB) and feature tables (~24MB) stay resident in L2.

#define TSIZE_MASK 0xFFFFFu        // TSIZE = 2^20
#define FDIM 32
#define QPW 4                      // queries per warp
#define LPQ 8                      // lanes per query (8 * float4 = 32 feats)

// PRIMES % TSIZE (exact int32 wraparound math, matches reference PM)
#define PM0 (73856093u % 1048576u)
#define PM1 (19349669u % 1048576u)
#define PM2 (83492791u % 1048576u)

struct LevelScalars {
    unsigned hx0, hx1, hy0, hy1, hz0, hz1;
    float fx, fy, fz;
};

__device__ __forceinline__ void level_prologue(float sx, float sy, float sz, LevelScalars& L)
{
    float bfx = floorf(sx), bfy = floorf(sy), bfz = floorf(sz);
    L.fx = sx - bfx; L.fy = sy - bfy; L.fz = sz - bfz;
    int bx = (int)bfx, by = (int)bfy, bz = (int)bfz;
    L.hx0 = (unsigned)bx * PM0; L.hx1 = L.hx0 + PM0;
    L.hy0 = (unsigned)by * PM1; L.hy1 = L.hy0 + PM1;
    L.hz0 = (unsigned)bz * PM2; L.hz1 = L.hz0 + PM2;
}

__device__ __forceinline__ void level_probe(const LevelScalars& L,
                                            const int* __restrict__ h2v, int v[8])
{
    unsigned xy00 = L.hx0 + L.hy0, xy01 = L.hx0 + L.hy1;
    unsigned xy10 = L.hx1 + L.hy0, xy11 = L.hx1 + L.hy1;
    v[0] = __ldg(h2v + ((xy00 + L.hz0) & TSIZE_MASK));
    v[1] = __ldg(h2v + ((xy00 + L.hz1) & TSIZE_MASK));
    v[2] = __ldg(h2v + ((xy01 + L.hz0) & TSIZE_MASK));
    v[3] = __ldg(h2v + ((xy01 + L.hz1) & TSIZE_MASK));
    v[4] = __ldg(h2v + ((xy10 + L.hz0) & TSIZE_MASK));
    v[5] = __ldg(h2v + ((xy10 + L.hz1) & TSIZE_MASK));
    v[6] = __ldg(h2v + ((xy11 + L.hz0) & TSIZE_MASK));
    v[7] = __ldg(h2v + ((xy11 + L.hz1) & TSIZE_MASK));
}

__device__ __forceinline__ void level_weights(const LevelScalars& L, float w[8])
{
    float wx0 = 1.0f - L.fx, wx1 = L.fx;
    float wy0 = 1.0f - L.fy, wy1 = L.fy;
    float wz0 = 1.0f - L.fz, wz1 = L.fz;
    float a00 = wx0 * wy0, a01 = wx0 * wy1, a10 = wx1 * wy0, a11 = wx1 * wy1;
    w[0] = a00 * wz0; w[1] = a00 * wz1;
    w[2] = a01 * wz0; w[3] = a01 * wz1;
    w[4] = a10 * wz0; w[5] = a10 * wz1;
    w[6] = a11 * wz0; w[7] = a11 * wz1;
}

// Two independent accumulator chains (even/odd corners) to halve FMA depth.
__device__ __forceinline__ void level_gather(const int v[8], const float w[8],
                                             const float* __restrict__ feats,
                                             int fcol, float4& out)
{
    float4 a = make_float4(0.f, 0.f, 0.f, 0.f);
    float4 b = make_float4(0.f, 0.f, 0.f, 0.f);
    #pragma unroll
    for (int c = 0; c < 8; c += 2) {
        if (v[c] >= 0) {
            float4 f = __ldg((const float4*)(feats + (size_t)v[c] * FDIM + fcol));
            a.x = fmaf(w[c], f.x, a.x);
            a.y = fmaf(w[c], f.y, a.y);
            a.z = fmaf(w[c], f.z, a.z);
            a.w = fmaf(w[c], f.w, a.w);
        }
        if (v[c + 1] >= 0) {
            float4 f = __ldg((const float4*)(feats + (size_t)v[c + 1] * FDIM + fcol));
            b.x = fmaf(w[c + 1], f.x, b.x);
            b.y = fmaf(w[c + 1], f.y, b.y);
            b.z = fmaf(w[c + 1], f.z, b.z);
            b.w = fmaf(w[c + 1], f.w, b.w);
        }
    }
    out.x = a.x + b.x; out.y = a.y + b.y; out.z = a.z + b.z; out.w = a.w + b.w;
}

__global__ void __launch_bounds__(256)
voxel_hash_kernel(const float* __restrict__ q,
                  const float* __restrict__ feats0,
                  const float* __restrict__ feats1,
                  const int*   __restrict__ h2v0,
                  const int*   __restrict__ h2v1,
                  float4* __restrict__ out4,
                  int M)
{
    int gtid  = blockIdx.x * blockDim.x + threadIdx.x;
    int lane  = gtid & 31;
    int warp  = gtid >> 5;
    int qsub  = lane >> 3;            // which of the 4 queries in this warp
    int flane = lane & 7;             // feature-quad index within the query
    int qidx  = warp * QPW + qsub;
    if (qidx >= M) return;

    // Streaming loads: query points are read exactly once — don't cache in L2.
    float qx = __ldcs(q + (size_t)qidx * 3 + 0);
    float qy = __ldcs(q + (size_t)qidx * 3 + 1);
    float qz = __ldcs(q + (size_t)qidx * 3 + 2);

    // Level 0: IEEE division (bit-match). Level 1: q/0.24 == (q/0.12)*0.5 exactly.
    float sx0 = __fdiv_rn(qx, 0.12f);
    float sy0 = __fdiv_rn(qy, 0.12f);
    float sz0 = __fdiv_rn(qz, 0.12f);
    float sx1 = sx0 * 0.5f, sy1 = sy0 * 0.5f, sz1 = sz0 * 0.5f;

    LevelScalars L0, L1;
    level_prologue(sx0, sy0, sz0, L0);
    level_prologue(sx1, sy1, sz1, L1);

    // Issue all 16 hash-table probes up front (MLP=16).
    int v0[8], v1[8];
    level_probe(L0, h2v0, v0);
    level_probe(L1, h2v1, v1);

    float w0[8], w1[8];
    level_weights(L0, w0);
    level_weights(L1, w1);

    int fcol = flane * 4;
    float4 r0, r1;
    level_gather(v0, w0, feats0, fcol, r0);
    level_gather(v1, w1, feats1, fcol, r1);

    // Streaming stores: output (128MB) must not evict the L2-resident tables.
    size_t obase = (size_t)qidx * 16 + flane;
    __stcs(out4 + obase,     r0);
    __stcs(out4 + obase + 8, r1);
}

extern "C" void kernel_launch(void* const* d_in, const int* in_sizes, int n_in,
                              void* d_out, int out_size)
{
    const float* q      = (const float*)d_in[0];
    const float* feats0 = (const float*)d_in[1];
    const float* feats1 = (const float*)d_in[2];
    const int*   h2v0   = (const int*)d_in[3];
    const int*   h2v1   = (const int*)d_in[4];
    float4* out = (float4*)d_out;

    int M = in_sizes[0] / 3;
    int threads = 256;
    long long total = (long long)M * LPQ;     // 8 lanes per query
    int blocks = (int)((total + threads - 1) / threads);
    voxel_hash_kernel<<<blocks, threads>>>(q, feats0, feats1, h2v0, h2v1, out, M);
}

// round 6
// speedup vs baseline: 1.8758x; 1.0090x over previous
#include <cuda_runtime.h>
#include <stdint.h>

// Voxel hash table, 2-level trilinear interpolation.
// 4 queries per warp; 8 lanes per query; each lane handles a float4 of features.
// Streaming (evict-first) loads/stores for the query + 128MB output streams so
// the hash tables (~8MB) and feature tables (~24MB) stay resident in L2.
// Register-lean: corner weights formed inline from 6 axis weights.

#define TSIZE_MASK 0xFFFFFu        // TSIZE = 2^20
#define FDIM 32
#define QPW 4                      // queries per warp
#define LPQ 8                      // lanes per query (8 * float4 = 32 feats)

// PRIMES % TSIZE (exact int32 wraparound math, matches reference PM)
#define PM0 (73856093u % 1048576u)
#define PM1 (19349669u % 1048576u)
#define PM2 (83492791u % 1048576u)

struct LevelScalars {
    unsigned hx0, hx1, hy0, hy1, hz0, hz1;
    float fx, fy, fz;
};

__device__ __forceinline__ void level_prologue(float sx, float sy, float sz, LevelScalars& L)
{
    float bfx = floorf(sx), bfy = floorf(sy), bfz = floorf(sz);
    L.fx = sx - bfx; L.fy = sy - bfy; L.fz = sz - bfz;
    int bx = (int)bfx, by = (int)bfy, bz = (int)bfz;
    L.hx0 = (unsigned)bx * PM0; L.hx1 = L.hx0 + PM0;
    L.hy0 = (unsigned)by * PM1; L.hy1 = L.hy0 + PM1;
    L.hz0 = (unsigned)bz * PM2; L.hz1 = L.hz0 + PM2;
}

__device__ __forceinline__ void level_probe(const LevelScalars& L,
                                            const int* __restrict__ h2v, int v[8])
{
    unsigned xy00 = L.hx0 + L.hy0, xy01 = L.hx0 + L.hy1;
    unsigned xy10 = L.hx1 + L.hy0, xy11 = L.hx1 + L.hy1;
    v[0] = __ldg(h2v + ((xy00 + L.hz0) & TSIZE_MASK));
    v[1] = __ldg(h2v + ((xy00 + L.hz1) & TSIZE_MASK));
    v[2] = __ldg(h2v + ((xy01 + L.hz0) & TSIZE_MASK));
    v[3] = __ldg(h2v + ((xy01 + L.hz1) & TSIZE_MASK));
    v[4] = __ldg(h2v + ((xy10 + L.hz0) & TSIZE_MASK));
    v[5] = __ldg(h2v + ((xy10 + L.hz1) & TSIZE_MASK));
    v[6] = __ldg(h2v + ((xy11 + L.hz0) & TSIZE_MASK));
    v[7] = __ldg(h2v + ((xy11 + L.hz1) & TSIZE_MASK));
}

// Gather with corner weights formed inline from the 6 axis weights.
// Two independent accumulator chains (even/odd corners) halve FMA depth.
__device__ __forceinline__ void level_gather(const int v[8], const LevelScalars& L,
                                             const float* __restrict__ feats,
                                             int fcol, float4& out)
{
    float wx0 = 1.0f - L.fx, wx1 = L.fx;
    float wy0 = 1.0f - L.fy, wy1 = L.fy;
    float wz0 = 1.0f - L.fz, wz1 = L.fz;

    float4 a = make_float4(0.f, 0.f, 0.f, 0.f);
    float4 b = make_float4(0.f, 0.f, 0.f, 0.f);
    #pragma unroll
    for (int c = 0; c < 8; c++) {
        float wxy = ((c & 4) ? wx1 : wx0) * ((c & 2) ? wy1 : wy0);
        float w   = wxy * ((c & 1) ? wz1 : wz0);
        if (v[c] >= 0) {
            float4 f = __ldg((const float4*)(feats + (size_t)v[c] * FDIM + fcol));
            if (c & 1) {
                b.x = fmaf(w, f.x, b.x); b.y = fmaf(w, f.y, b.y);
                b.z = fmaf(w, f.z, b.z); b.w = fmaf(w, f.w, b.w);
            } else {
                a.x = fmaf(w, f.x, a.x); a.y = fmaf(w, f.y, a.y);
                a.z = fmaf(w, f.z, a.z); a.w = fmaf(w, f.w, a.w);
            }
        }
    }
    out.x = a.x + b.x; out.y = a.y + b.y; out.z = a.z + b.z; out.w = a.w + b.w;
}

__global__ void __launch_bounds__(256, 6)
voxel_hash_kernel(const float* __restrict__ q,
                  const float* __restrict__ feats0,
                  const float* __restrict__ feats1,
                  const int*   __restrict__ h2v0,
                  const int*   __restrict__ h2v1,
                  float4* __restrict__ out4,
                  int M)
{
    int gtid  = blockIdx.x * blockDim.x + threadIdx.x;
    int lane  = gtid & 31;
    int warp  = gtid >> 5;
    int qsub  = lane >> 3;            // which of the 4 queries in this warp
    int flane = lane & 7;             // feature-quad index within the query
    int qidx  = warp * QPW + qsub;
    if (qidx >= M) return;

    // Streaming loads: query points are read exactly once — don't pollute L2.
    float qx = __ldcs(q + (size_t)qidx * 3 + 0);
    float qy = __ldcs(q + (size_t)qidx * 3 + 1);
    float qz = __ldcs(q + (size_t)qidx * 3 + 2);

    // Level 0: IEEE division (bit-match). Level 1: q/0.24 == (q/0.12)*0.5 exactly
    // (f32(0.24) is exactly 2*f32(0.12); scaling by 2 commutes with rn-division).
    float sx0 = __fdiv_rn(qx, 0.12f);
    float sy0 = __fdiv_rn(qy, 0.12f);
    float sz0 = __fdiv_rn(qz, 0.12f);

    LevelScalars L0, L1;
    level_prologue(sx0, sy0, sz0, L0);
    level_prologue(sx0 * 0.5f, sy0 * 0.5f, sz0 * 0.5f, L1);

    // Issue all 16 hash-table probes up front (MLP=16).
    int v0[8], v1[8];
    level_probe(L0, h2v0, v0);
    level_probe(L1, h2v1, v1);

    int fcol = flane * 4;
    float4 r0, r1;
    level_gather(v0, L0, feats0, fcol, r0);
    level_gather(v1, L1, feats1, fcol, r1);

    // Streaming stores: the 128MB output must not evict the L2-resident tables.
    size_t obase = (size_t)qidx * 16 + flane;
    __stcs(out4 + obase,     r0);
    __stcs(out4 + obase + 8, r1);
}

extern "C" void kernel_launch(void* const* d_in, const int* in_sizes, int n_in,
                              void* d_out, int out_size)
{
    const float* q      = (const float*)d_in[0];
    const float* feats0 = (const float*)d_in[1];
    const float* feats1 = (const float*)d_in[2];
    const int*   h2v0   = (const int*)d_in[3];
    const int*   h2v1   = (const int*)d_in[4];
    float4* out = (float4*)d_out;

    int M = in_sizes[0] / 3;
    int threads = 256;
    long long total = (long long)M * LPQ;     // 8 lanes per query
    int blocks = (int)((total + threads - 1) / threads);
    voxel_hash_kernel<<<blocks, threads>>>(q, feats0, feats1, h2v0, h2v1, out, M);
}